// round 17
// baseline (speedup 1.0000x reference)
#include <cuda_runtime.h>
#include <cstdint>
#include <math.h>

// SoftPolygon B=32, P=32, 128x128.  out[b,y,x] = sigmoid(min_seg_sq * io)
//
// v17: block = 4 rows x 2 half-spans (256 thr, 8 warps), with per-EDGE
//      row-independent constants computed ONCE per block by warp 0:
//        {x1, y1, dx, dy, A=dx*inv, DyInv=dy*inv, S=parity slope, ty_prev,
//         ga0^2, ga1^2}  (1.5 KB smem)
//      Per-row work becomes division-free: xint = fma(S, ys1, x1);
//      dot = fma(xsA, A, ys1*DyInv); dva = fma(ys1, ys1, ga^2).
//      Mainloop/epilogue = v16 (compacted edges, CULL_T=6.25, tanh sigmoid,
//      float2 stores).
//
// Safety: parity flips need |gx-xint| < err, and the crossing point lies ON
// that edge, so affected pixels sit within err of the boundary -> both
// outputs ~0.5 (flip error ~err^2). Culled edges are >2.5px from every span
// pixel -> saturation error ~1e-4 L2-rel. All << 1e-3 gate.

namespace {

constexpr int NB  = 32;
constexpr int NP  = 32;
constexpr int NH  = 128;
constexpr int NW  = 128;
constexpr int RPB = 4;             // rows per block
constexpr int NWARP = 2 * RPB;     // 8 warps
constexpr float CULL_T = 6.25f;    // sq-distance saturation threshold (2.5px)

__device__ __forceinline__ float sigmoid_fast(float v) {
    float t;
    asm("tanh.approx.f32 %0, %1;" : "=f"(t) : "f"(0.5f * v));
    return fmaf(0.5f, t, 0.5f);
}

__global__ __launch_bounds__(256, 8) void soft_poly_kernel(
    const float* __restrict__ verts,   // (B, P, 2)
    float* __restrict__ out)           // (B, H, W)
{
    const int b    = blockIdx.y;
    const int row0 = blockIdx.x * RPB;
    const int tid  = threadIdx.x;
    const int w    = tid >> 5;         // warp 0..7
    const int lane = tid & 31;
    const int r    = w >> 1;           // local row 0..3
    const int hp   = w & 1;            // column half 0..1
    const int row  = row0 + r;
    const float gy = (float)row;

    __shared__ float  vbuf[NP * 2];            // interleaved x,y
    __shared__ float4 cE0[NP];                 // {x1, y1, dx, dy}
    __shared__ float4 cE1[NP];                 // {A, DyInv, S, ty_prev}
    __shared__ float2 cE2[NP];                 // {ga0^2, ga1^2}
    __shared__ float4 sA[NWARP][NP];           // compacted {x1, A, c0, dx}
    __shared__ float2 sB[NWARP][NP];           // compacted {dy, ys1}

    if (tid < NP * 2) vbuf[tid] = verts[(size_t)b * NP * 2 + tid];
    __syncthreads();

    // ---- stage 2: row-independent per-edge constants (warp 0 only) ----
    if (w == 0) {
        const int i  = lane;
        const int jp = (i + NP - 1) & (NP - 1);   // prev vertex
        const int kn = (i + 1) & (NP - 1);        // next vertex
        const float x1 = vbuf[2 * i],  y1 = vbuf[2 * i + 1];
        const float xp = vbuf[2 * jp], yp = vbuf[2 * jp + 1];
        const float xn = vbuf[2 * kn], yn = vbuf[2 * kn + 1];

        const float dx = xn - x1, dy = yn - y1;
        const float sq  = dx * dx + dy * dy + 1e-5f;
        const float inv = __fdividef(1.0f, sq);
        const float S   = __fdividef(xp - x1, yp - y1);  // parity-edge slope

        // span gaps of vertex v_i for the two halves [0,63], [64,127]
        const float ga0 = fmaxf(fmaxf(-x1, x1 - 63.0f), 0.0f);
        const float ga1 = fmaxf(fmaxf(64.0f - x1, x1 - 127.0f), 0.0f);

        cE0[i] = make_float4(x1, y1, dx, dy);
        cE1[i] = make_float4(dx * inv, dy * inv, S, yp);
        cE2[i] = make_float2(ga0 * ga0, ga1 * ga1);
    }
    __syncthreads();

    // ---- stage 3: per-(row, half) precompute; edge = lane ----
    const unsigned full = 0xffffffffu;
    const float sxa = (float)(hp * 64);
    unsigned int pmA, pmB;   // parity words for this warp's 2 column groups
    int nkeep;               // surviving edge count (warp-uniform)
    {
        const float4 e0 = cE0[lane];    // {x1, y1, dx, dy}
        const float4 e1 = cE1[lane];    // {A, DyInv, S, ty_prev}
        const float2 e2 = cE2[lane];    // {ga0^2, ga1^2}
        const float x1 = e0.x, y1 = e0.y, dx = e0.z, dy = e0.w;
        const float A = e1.x, DyInv = e1.y, S = e1.z, typ = e1.w;

        const float ys1 = gy - y1;

        // crossing threshold: xint = S*(gy - fy) + fx  (division-free)
        const bool cond = (y1 > gy) != (typ > gy);
        float xint = fmaf(S, ys1, x1);
        const bool crossFlag = cond && (xint >= sxa) && (xint <= sxa + 63.0f);
        if (!cond) xint = -1.0f;
        const float xc = fminf(fmaxf(ceilf(xint), 0.0f), 128.0f);
        const int ci = (int)xc - hp * 64;

        const int nA = min(max(ci,      0), 32);
        const int nB = min(max(ci - 32, 0), 32);
        const unsigned int mA = (unsigned int)((1ull << nA) - 1ull);
        const unsigned int mB = (unsigned int)((1ull << nB) - 1ull);
        pmA = __reduce_xor_sync(full, mA);
        pmB = __reduce_xor_sync(full, mB);

        // ---- EXACT cull: dist(span segment, edge segment)^2 <= CULL_T ----
        const float gasq = hp ? e2.y : e2.x;
        const float dva  = fmaf(ys1, ys1, gasq);
        const float dvb  = __shfl_sync(full, dva, (lane + 1) & 31);

        const float c0  = ys1 * DyInv;           // reused for scatter below
        const float xsA = sxa - x1;
        const float dot = fmaf(xsA, A, c0);
        const float tA  = __saturatef(dot);
        const float xpA = fmaf(-tA, dx, xsA);
        const float ypA = fmaf(-tA, dy, ys1);
        const float dpa = fmaf(xpA, xpA, ypA * ypA);
        const float tB  = __saturatef(fmaf(63.0f, A, dot));
        const float xsB = xsA + 63.0f;
        const float xpB = fmaf(-tB, dx, xsB);
        const float ypB = fmaf(-tB, dy, ys1);
        const float dpb = fmaf(xpB, xpB, ypB * ypB);
        const bool isect =
            (bool)__shfl_sync(full, (int)crossFlag, (lane + 1) & 31);

        const float best = fminf(fminf(dva, dvb), fminf(dpa, dpb));
        const bool keep = isect || (best <= CULL_T);
        const unsigned int kmask = __ballot_sync(full, keep);
        nkeep = __popc(kmask);

        if (keep) {   // compacted scatter: kept lane -> dense slot
            const int pos = __popc(kmask & ((1u << lane) - 1u));
            sA[w][pos] = make_float4(x1, A, c0, dx);
            sB[w][pos] = make_float2(dy, ys1);
        }
    }
    __syncwarp();   // sA/sB written and read by the same warp

    // ---- mainloop: compacted edges, adjacent-column pixel pair per lane ----
    const float gx0 = sxa + (float)(2 * lane);
    const float gx1 = gx0 + 1.0f;
    float mn0 = 3.402823466e38f, mn1 = mn0;

#define PIX(A_, B_, GX, MN) do {                               \
        const float xs  = (GX) - (A_).x;                       \
        const float dot = fmaf(xs, (A_).y, (A_).z);            \
        const float t   = __saturatef(dot);                    \
        const float xp  = fmaf(-t, (A_).w, xs);                \
        const float yp  = fmaf(-t, (B_).x, (B_).y);            \
        const float d   = fmaf(xp, xp, yp * yp);               \
        (MN) = fminf((MN), d);                                 \
    } while (0)

    int i = 0;
    for (; i + 2 <= nkeep; i += 2) {
        const float4 a0 = sA[w][i],     a1 = sA[w][i + 1];
        const float2 b0 = sB[w][i],     b1 = sB[w][i + 1];
        PIX(a0, b0, gx0, mn0);
        PIX(a0, b0, gx1, mn1);
        PIX(a1, b1, gx0, mn0);
        PIX(a1, b1, gx1, mn1);
    }
    if (i < nkeep) {
        const float4 a0 = sA[w][i];
        const float2 b0 = sB[w][i];
        PIX(a0, b0, gx0, mn0);
        PIX(a0, b0, gx1, mn1);
    }
#undef PIX

    // ---- epilogue: parity pair from 64-bit concat, fast sigmoid, STG.64 ----
    const unsigned long long p64 =
        (unsigned long long)pmA | ((unsigned long long)pmB << 32);
    const unsigned int pair = (unsigned int)(p64 >> (2 * lane)) & 3u;
    const float io0 = (pair & 1u) ? 1.0f : -1.0f;
    const float io1 = (pair & 2u) ? 1.0f : -1.0f;

    float2* op = (float2*)(out + ((size_t)b * NH + row) * NW + hp * 64) + lane;
    *op = make_float2(sigmoid_fast(mn0 * io0), sigmoid_fast(mn1 * io1));
}

}  // namespace

extern "C" void kernel_launch(void* const* d_in, const int* in_sizes, int n_in,
                              void* d_out, int out_size) {
    const float* verts = (const float*)d_in[0];
    float* out = (float*)d_out;
    dim3 grid(NH / RPB, NB);   // 32 x 32 = 1024 blocks, 256 threads each
    soft_poly_kernel<<<grid, 256>>>(verts, out);
}